// round 7
// baseline (speedup 1.0000x reference)
#include <cuda_runtime.h>
#include <cstdint>

#define DIM    1024
#define KC     32
#define MROWS  64
#define TPB    128
#define KCH    64
#define NCH    (DIM / KCH)        // 16 chunks
#define PITCHB 144                // bytes per smem row: 128 data + 16 pad (9x16B)
// stage byte offsets
#define AH_OFF 0
#define AL_OFF (MROWS * PITCHB)               // 9216
#define BH_OFF (2 * MROWS * PITCHB)           // 18432
#define BL_OFF (BH_OFF + KC * PITCHB)         // 23040
#define STAGE  (BL_OFF + KC * PITCHB)         // 27648 B
#define SMEM_TOTAL (2 * STAGE + KC * 4)       // 55424 B

static __device__ __forceinline__ uint32_t s2u(const void* p) {
    uint32_t a;
    asm("{ .reg .u64 t; cvta.to.shared.u64 t, %1; cvt.u32.u64 %0, t; }" : "=r"(a) : "l"(p));
    return a;
}

// split fp32 pair into bf16x2 hi + bf16x2 lo (RN both stages); low half = first arg
static __device__ __forceinline__ void split2(float x0, float x1,
                                              uint32_t& hi2, uint32_t& lo2) {
    asm("cvt.rn.bf16x2.f32 %0, %1, %2;" : "=r"(hi2) : "f"(x1), "f"(x0));
    float h0 = __uint_as_float(hi2 << 16);
    float h1 = __uint_as_float(hi2 & 0xFFFF0000u);
    float l0 = x0 - h0, l1 = x1 - h1;
    asm("cvt.rn.bf16x2.f32 %0, %1, %2;" : "=r"(lo2) : "f"(l1), "f"(l0));
}

static __device__ __forceinline__ void mma_bf16(float* c, const uint32_t* a,
                                                uint32_t b0, uint32_t b1) {
    asm volatile(
        "mma.sync.aligned.m16n8k16.row.col.f32.bf16.bf16.f32 "
        "{%0,%1,%2,%3}, {%4,%5,%6,%7}, {%8,%9}, {%0,%1,%2,%3};"
        : "+f"(c[0]), "+f"(c[1]), "+f"(c[2]), "+f"(c[3])
        : "r"(a[0]), "r"(a[1]), "r"(a[2]), "r"(a[3]), "r"(b0), "r"(b1));
}

#define LDSM4(r, addr) \
    asm volatile("ldmatrix.sync.aligned.m8n8.x4.shared.b16 {%0,%1,%2,%3}, [%4];" \
                 : "=r"((r)[0]), "=r"((r)[1]), "=r"((r)[2]), "=r"((r)[3]) : "r"(addr))

#define STSV2(addr, r0, r1) \
    asm volatile("st.shared.v2.u32 [%0], {%1,%2};" :: "r"(addr), "r"(r0), "r"(r1) : "memory")

// split a float4 and store hi/lo bf16x2 pairs to the two buffers
static __device__ __forceinline__ void splitStore(float4 v, uint32_t aHi, uint32_t aLo) {
    uint32_t h0, l0, h1, l1;
    split2(v.x, v.y, h0, l0);
    split2(v.z, v.w, h1, l1);
    STSV2(aHi, h0, h1);
    STSV2(aLo, l0, l1);
}

__global__ __launch_bounds__(TPB, 4)
void nkm_mma(const float* __restrict__ X, const float* __restrict__ C,
             float* __restrict__ out, int N) {
    extern __shared__ char smem[];
    const uint32_t sb = s2u(smem);
    float* sSq = reinterpret_cast<float*>(smem + 2 * STAGE);

    const int tid  = threadIdx.x;
    const int w    = tid >> 5;
    const int l    = tid & 31;
    const int g    = l >> 2;         // fragment row group 0..7
    const int ql   = l & 3;          // fragment k/col phase 0..3
    const int blockBase = blockIdx.x * MROWS;

    const float4* __restrict__ X4 = reinterpret_cast<const float4*>(X);
    const float4* __restrict__ C4 = reinterpret_cast<const float4*>(C);

    // ---- loader constants ----
    // X: chunk = 64 rows x 16 float4; j-th piece: idx=j*128+tid -> row=8j+(tid>>4), col4=tid&15
    const int xRow = tid >> 4;           // + 8j
    const int xC4  = tid & 15;
    int xg[8];
    uint32_t stsX[8];
#pragma unroll
    for (int j = 0; j < 8; j++) {
        int row = 8 * j + xRow;
        int gr  = blockBase + row;
        if (gr >= N) gr = N - 1;          // clamp; outputs guarded
        xg[j]   = gr * (DIM / 4) + xC4;   // + kt*16 per chunk
        stsX[j] = (uint32_t)(row * PITCHB + xC4 * 8);
    }
    // C: chunk = 32 rows x 16 float4; j=0..3: row=8j+(tid>>4)
    int cg[4];
    uint32_t stsC[4];
#pragma unroll
    for (int j = 0; j < 4; j++) {
        int row = 8 * j + xRow;
        cg[j]   = row * (DIM / 4) + xC4;
        stsC[j] = (uint32_t)(row * PITCHB + xC4 * 8);
    }

    // ---- ldmatrix address constants (byte offsets within a stage) ----
    const int mat  = l >> 3;
    const uint32_t aOff = (uint32_t)((16 * w + (l & 7) + 8 * (mat & 1)) * PITCHB
                                     + ((mat >> 1) * 16));
    const uint32_t bOff = (uint32_t)(((l & 7) + 8 * (mat >> 1)) * PITCHB
                                     + ((mat & 1) * 16));

    float acc[4][4];                  // [ntile][frag]: rows {g,g+8} x classes {8nt+2ql, +1}
#pragma unroll
    for (int nt = 0; nt < 4; nt++)
#pragma unroll
        for (int i = 0; i < 4; i++) acc[nt][i] = 0.0f;
    float sq[4] = {0.f, 0.f, 0.f, 0.f};   // ||mu||^2 partials for rows 8j+xRow

    // ---- prologue: chunk 0 -> buf 0 ----
    {
        const uint32_t bw = sb;
#pragma unroll
        for (int j = 0; j < 8; j++) {
            float4 v = X4[xg[j]];
            splitStore(v, bw + AH_OFF + stsX[j], bw + AL_OFF + stsX[j]);
        }
#pragma unroll
        for (int j = 0; j < 4; j++) {
            float4 v = C4[cg[j]];
            sq[j] += v.x * v.x + v.y * v.y + v.z * v.z + v.w * v.w;
            splitStore(v, bw + BH_OFF + stsC[j], bw + BL_OFF + stsC[j]);
        }
    }
    __syncthreads();

    // ---- main loop over 16 chunks ----
#pragma unroll 1
    for (int kt = 0; kt < NCH; kt++) {
        const bool more = (kt + 1 < NCH);
        const int kc4 = (kt + 1) * (KCH / 4);
        const uint32_t br = sb + (uint32_t)(kt & 1) * STAGE;          // read buffer
        const uint32_t bw = sb + (uint32_t)((kt + 1) & 1) * STAGE;    // write buffer

        // group A prefetch (X j=0..3)
        float4 xa[4];
        if (more) {
#pragma unroll
            for (int j = 0; j < 4; j++) xa[j] = X4[xg[j] + kc4];
        }

        // compute k-halves s=0,1
#pragma unroll
        for (int s = 0; s < 2; s++) {
            uint32_t ah[4], al4[4];
            LDSM4(ah,  br + AH_OFF + aOff + 32u * s);
            LDSM4(al4, br + AL_OFF + aOff + 32u * s);
#pragma unroll
            for (int p = 0; p < 2; p++) {
                uint32_t bh[4], bl[4];
                LDSM4(bh, br + BH_OFF + bOff + 2304u * p + 32u * s);
                LDSM4(bl, br + BL_OFF + bOff + 2304u * p + 32u * s);
                mma_bf16(acc[2 * p],     ah,  bh[0], bh[1]);
                mma_bf16(acc[2 * p],     ah,  bl[0], bl[1]);
                mma_bf16(acc[2 * p],     al4, bh[0], bh[1]);
                mma_bf16(acc[2 * p + 1], ah,  bh[2], bh[3]);
                mma_bf16(acc[2 * p + 1], ah,  bl[2], bl[3]);
                mma_bf16(acc[2 * p + 1], al4, bh[2], bh[3]);
            }
        }

        // group B prefetch (X j=4..7, C), store group A
        float4 xb[4], cr[4];
        if (more) {
#pragma unroll
            for (int j = 0; j < 4; j++) xb[j] = X4[xg[j + 4] + kc4];
#pragma unroll
            for (int j = 0; j < 4; j++) cr[j] = C4[cg[j] + kc4];
#pragma unroll
            for (int j = 0; j < 4; j++)
                splitStore(xa[j], bw + AH_OFF + stsX[j], bw + AL_OFF + stsX[j]);
        }

        // compute k-halves s=2,3
#pragma unroll
        for (int s = 2; s < 4; s++) {
            uint32_t ah[4], al4[4];
            LDSM4(ah,  br + AH_OFF + aOff + 32u * s);
            LDSM4(al4, br + AL_OFF + aOff + 32u * s);
#pragma unroll
            for (int p = 0; p < 2; p++) {
                uint32_t bh[4], bl[4];
                LDSM4(bh, br + BH_OFF + bOff + 2304u * p + 32u * s);
                LDSM4(bl, br + BL_OFF + bOff + 2304u * p + 32u * s);
                mma_bf16(acc[2 * p],     ah,  bh[0], bh[1]);
                mma_bf16(acc[2 * p],     ah,  bl[0], bl[1]);
                mma_bf16(acc[2 * p],     al4, bh[0], bh[1]);
                mma_bf16(acc[2 * p + 1], ah,  bh[2], bh[3]);
                mma_bf16(acc[2 * p + 1], ah,  bl[2], bl[3]);
                mma_bf16(acc[2 * p + 1], al4, bh[2], bh[3]);
            }
        }

        // store group B
        if (more) {
#pragma unroll
            for (int j = 0; j < 4; j++)
                splitStore(xb[j], bw + AH_OFF + stsX[j + 4], bw + AL_OFF + stsX[j + 4]);
#pragma unroll
            for (int j = 0; j < 4; j++) {
                sq[j] += cr[j].x * cr[j].x + cr[j].y * cr[j].y
                       + cr[j].z * cr[j].z + cr[j].w * cr[j].w;
                splitStore(cr[j], bw + BH_OFF + stsC[j], bw + BL_OFF + stsC[j]);
            }
        }
        __syncthreads();
    }

    // ---- ||mu||^2 reduce: 16 threads per class row (width-16 shfl) ----
#pragma unroll
    for (int j = 0; j < 4; j++) {
        sq[j] += __shfl_down_sync(0xffffffffu, sq[j], 8, 16);
        sq[j] += __shfl_down_sync(0xffffffffu, sq[j], 4, 16);
        sq[j] += __shfl_down_sync(0xffffffffu, sq[j], 2, 16);
        sq[j] += __shfl_down_sync(0xffffffffu, sq[j], 1, 16);
    }
    if ((tid & 15) == 0) {
#pragma unroll
        for (int j = 0; j < 4; j++) sSq[8 * j + xRow] = sq[j];
    }
    __syncthreads();

    // ---- epilogue: s = 2*dot - sq ; top2 per row; merge across quad ----
    const float NEG_INF = -__int_as_float(0x7f800000);
    float m1[2] = {NEG_INF, NEG_INF};
    float m2[2] = {NEG_INF, NEG_INF};
#pragma unroll
    for (int nt = 0; nt < 4; nt++) {
        const int c0 = 8 * nt + ql * 2;
        const float q0 = sSq[c0], q1 = sSq[c0 + 1];
        float s;
        s = 2.0f * acc[nt][0] - q0;
        if (s > m1[0]) { m2[0] = m1[0]; m1[0] = s; } else if (s > m2[0]) m2[0] = s;
        s = 2.0f * acc[nt][1] - q1;
        if (s > m1[0]) { m2[0] = m1[0]; m1[0] = s; } else if (s > m2[0]) m2[0] = s;
        s = 2.0f * acc[nt][2] - q0;
        if (s > m1[1]) { m2[1] = m1[1]; m1[1] = s; } else if (s > m2[1]) m2[1] = s;
        s = 2.0f * acc[nt][3] - q1;
        if (s > m1[1]) { m2[1] = m1[1]; m1[1] = s; } else if (s > m2[1]) m2[1] = s;
    }
#pragma unroll
    for (int delta = 1; delta <= 2; delta <<= 1) {
#pragma unroll
        for (int r = 0; r < 2; r++) {
            float om1 = __shfl_xor_sync(0xffffffffu, m1[r], delta);
            float om2 = __shfl_xor_sync(0xffffffffu, m2[r], delta);
            float nm1 = fmaxf(m1[r], om1);
            float nm2 = fmaxf(fminf(m1[r], om1), fmaxf(m2[r], om2));
            m1[r] = nm1;
            m2[r] = nm2;
        }
    }
    if (ql == 0) {
        int r0 = blockBase + 16 * w + g;
        if (r0 < N)     out[r0]     = m1[0] - m2[0];
        if (r0 + 8 < N) out[r0 + 8] = m1[1] - m2[1];
    }
}

extern "C" void kernel_launch(void* const* d_in, const int* in_sizes, int n_in,
                              void* d_out, int out_size) {
    const float* X = (const float*)d_in[0];   // [N, 1024]
    const float* C = (const float*)d_in[1];   // [32, 1024]
    float* out = (float*)d_out;               // [N]
    int N = in_sizes[0] / DIM;
    int nb = (N + MROWS - 1) / MROWS;

    cudaFuncSetAttribute(nkm_mma, cudaFuncAttributeMaxDynamicSharedMemorySize, SMEM_TOTAL);
    nkm_mma<<<nb, TPB, SMEM_TOTAL>>>(X, C, out, N);
}